// round 2
// baseline (speedup 1.0000x reference)
#include <cuda_runtime.h>

// Problem constants (fixed by the reference: B=8, N=M=4096, C=3)
#define BATCH   8
#define NPTS    4096
#define TILE    1024
#define THREADS 64
#define NBLK_X  (NPTS / THREADS)            // 64
#define NPART   (NBLK_X * BATCH * 2)        // 1024 partial sums

// Per-block partial sums of per-point NN distances (no device allocs allowed)
__device__ float g_partial[NPART];

#define ABS2 0x7FFFFFFF7FFFFFFFULL

__device__ __forceinline__ unsigned long long pack2(float lo, float hi) {
    unsigned long long r;
    asm("mov.b64 %0, {%1, %2};" : "=l"(r) : "f"(lo), "f"(hi));
    return r;
}
__device__ __forceinline__ void unpack2(unsigned long long v, float& lo, float& hi) {
    asm("mov.b64 {%0, %1}, %2;" : "=f"(lo), "=f"(hi) : "l"(v));
}
// Blackwell double-pumped FP32: 2 adds per issue slot (SASS FADD2)
__device__ __forceinline__ unsigned long long addf32x2(unsigned long long a,
                                                       unsigned long long b) {
    unsigned long long r;
    asm("add.rn.f32x2 %0, %1, %2;" : "=l"(r) : "l"(a), "l"(b));
    return r;
}

// One thread = one query point. y-tile staged in smem NEGATED and in SoA form,
// so |x - y| = |x + (-y)| uses only add.rn.f32x2 + 64-bit AND (abs) + FMNMX.
// blockIdx.z = 0: queries=x, targets=y; z=1: queries=y, targets=x.
__global__ __launch_bounds__(THREADS)
void chamfer_pass_kernel(const float* __restrict__ x,
                         const float* __restrict__ y) {
    __shared__ float4 s4[3 * TILE / 4];          // SoA: [-x| -y| -z] coords
    __shared__ float warp_s[THREADS / 32];

    float* snx = (float*)s4;
    float* sny = snx + TILE;
    float* snz = sny + TILE;

    const int b   = blockIdx.y;
    const int dir = blockIdx.z;
    const float* A    = dir == 0 ? x : y;
    const float* Bset = dir == 0 ? y : x;

    const int i = blockIdx.x * THREADS + threadIdx.x;
    const float* Ab = A    + ((size_t)b * NPTS + i) * 3;
    const float* Bb = Bset + (size_t)b * NPTS * 3;

    const float x0 = Ab[0], x1 = Ab[1], x2 = Ab[2];
    const unsigned long long X0 = pack2(x0, x0);
    const unsigned long long X1 = pack2(x1, x1);
    const unsigned long long X2 = pack2(x2, x2);

    float m0 = 1e30f, m1 = 1e30f, m2 = 1e30f, m3 = 1e30f;

    for (int t = 0; t < NPTS; t += TILE) {
        __syncthreads();
        for (int k = threadIdx.x; k < TILE; k += THREADS) {
            const float* p = Bb + (size_t)(t + k) * 3;
            snx[k] = -p[0];
            sny[k] = -p[1];
            snz[k] = -p[2];
        }
        __syncthreads();

        const ulonglong2* px = (const ulonglong2*)snx;
        const ulonglong2* py = (const ulonglong2*)sny;
        const ulonglong2* pz = (const ulonglong2*)snz;

        #pragma unroll 4
        for (int g = 0; g < TILE / 4; g++) {
            // LDS.128 broadcast (all lanes same address): 4 y-points per array
            ulonglong2 vx = px[g];
            ulonglong2 vy = py[g];
            ulonglong2 vz = pz[g];

            // pairs (4g, 4g+1)
            unsigned long long t0 = addf32x2(X0, vx.x) & ABS2;
            unsigned long long t1 = addf32x2(X1, vy.x) & ABS2;
            unsigned long long t2 = addf32x2(X2, vz.x) & ABS2;
            unsigned long long dA = addf32x2(addf32x2(t0, t1), t2);

            // pairs (4g+2, 4g+3)
            unsigned long long u0 = addf32x2(X0, vx.y) & ABS2;
            unsigned long long u1 = addf32x2(X1, vy.y) & ABS2;
            unsigned long long u2 = addf32x2(X2, vz.y) & ABS2;
            unsigned long long dB = addf32x2(addf32x2(u0, u1), u2);

            float a, bb, c, d;
            unpack2(dA, a, bb);
            unpack2(dB, c, d);
            m0 = fminf(m0, a);
            m1 = fminf(m1, bb);
            m2 = fminf(m2, c);
            m3 = fminf(m3, d);
        }
    }

    // Per-block deterministic partial sum of the 64 per-point minima
    float m = fminf(fminf(m0, m1), fminf(m2, m3));
    #pragma unroll
    for (int o = 16; o > 0; o >>= 1)
        m += __shfl_down_sync(0xffffffffu, m, o);
    if ((threadIdx.x & 31) == 0) warp_s[threadIdx.x >> 5] = m;
    __syncthreads();
    if (threadIdx.x == 0) {
        int flat = blockIdx.x + NBLK_X * (blockIdx.y + BATCH * blockIdx.z);
        g_partial[flat] = warp_s[0] + warp_s[1];
    }
}

// Sum 1024 partials -> mean_x + mean_y (uniform sizes: flat mean over B*N each)
__global__ void chamfer_reduce_kernel(float* __restrict__ out) {
    __shared__ float warp_s[8];
    const int tid = threadIdx.x;          // 256 threads

    float s = 0.0f;
    #pragma unroll
    for (int k = 0; k < NPART / 256; k++)
        s += g_partial[tid + 256 * k];

    #pragma unroll
    for (int o = 16; o > 0; o >>= 1)
        s += __shfl_down_sync(0xffffffffu, s, o);
    if ((tid & 31) == 0) warp_s[tid >> 5] = s;
    __syncthreads();

    if (tid < 32) {
        float v = (tid < 8) ? warp_s[tid] : 0.0f;
        #pragma unroll
        for (int o = 4; o > 0; o >>= 1)
            v += __shfl_down_sync(0xffffffffu, v, o);
        if (tid == 0)
            out[0] = v * (1.0f / (float)(BATCH * NPTS));
    }
}

extern "C" void kernel_launch(void* const* d_in, const int* in_sizes, int n_in,
                              void* d_out, int out_size) {
    const float* x = (const float*)d_in[0];
    const float* y = (const float*)d_in[1];
    float* out = (float*)d_out;
    (void)in_sizes; (void)n_in; (void)out_size;

    dim3 grid(NBLK_X, BATCH, 2);          // 1024 blocks of 64 threads
    chamfer_pass_kernel<<<grid, THREADS>>>(x, y);
    chamfer_reduce_kernel<<<1, 256>>>(out);
}